// round 1
// baseline (speedup 1.0000x reference)
#include <cuda_runtime.h>

#define HW   (512*512)
#define W    512
#define NCH  48            // 16 batches * 3 channels
#define FW   23
#define PAD  11
#define TILE 32
#define SH   (TILE + 2*PAD)   // 54
#define NBLK 1024

// scratch (no cudaMalloc allowed)
__device__ float g_res[(size_t)NCH * HW];
__device__ float g_med[NCH];
__device__ float g_lo[NCH];
__device__ float g_hi[NCH];
__device__ float g_k1[FW];

// ---------------------------------------------------------------------------
// float <-> order-preserving uint
// ---------------------------------------------------------------------------
__device__ __forceinline__ unsigned f2u(float f) {
    unsigned u = __float_as_uint(f);
    return (u & 0x80000000u) ? ~u : (u | 0x80000000u);
}
__device__ __forceinline__ float u2f(unsigned u) {
    return __uint_as_float((u & 0x80000000u) ? (u ^ 0x80000000u) : ~u);
}

// ---------------------------------------------------------------------------
// block-wide radix select: finds sorted[rank] (and sorted[rank+1] if needed)
// for up to NR ranks simultaneously. One block, NBLK threads.
// ---------------------------------------------------------------------------
template <int NR, bool TRUNC>
__device__ void radix_select(const float* __restrict__ data, int n,
                             const int* ranks, float* v_out, float* v1_out,
                             bool need_next)
{
    __shared__ unsigned hist[NR][2048];
    __shared__ unsigned pref[NR];
    __shared__ int      below[NR];
    __shared__ unsigned vsel[NR];
    __shared__ int      clt[NR], ceq[NR];
    __shared__ unsigned nmin[NR];

    const int tid = threadIdx.x;

    // ---- pass 1: top 11 bits (rank-independent, one shared hist) ----
    for (int i = tid; i < 2048; i += NBLK) hist[0][i] = 0;
    __syncthreads();
    for (int i = tid; i < n; i += NBLK) {
        float f = data[i];
        if (TRUNC) f = truncf(f * 256.0f) * (1.0f / 256.0f);
        atomicAdd(&hist[0][f2u(f) >> 21], 1u);
    }
    __syncthreads();
    if (tid == 0) {
        for (int rr = 0; rr < NR; rr++) {
            int k = ranks[rr];
            unsigned cum = 0; int b = 0;
            for (; b < 2048; b++) { unsigned c = hist[0][b]; if ((int)(cum + c) > k) break; cum += c; }
            pref[rr] = (unsigned)b << 21;
            below[rr] = (int)cum;
        }
    }
    __syncthreads();

    // ---- pass 2: bits [20:10], per-rank hist ----
    for (int rr = 0; rr < NR; rr++)
        for (int i = tid; i < 2048; i += NBLK) hist[rr][i] = 0;
    __syncthreads();
    for (int i = tid; i < n; i += NBLK) {
        float f = data[i];
        if (TRUNC) f = truncf(f * 256.0f) * (1.0f / 256.0f);
        unsigned u = f2u(f);
        #pragma unroll
        for (int rr = 0; rr < NR; rr++)
            if ((u >> 21) == (pref[rr] >> 21))
                atomicAdd(&hist[rr][(u >> 10) & 2047], 1u);
    }
    __syncthreads();
    if (tid == 0) {
        for (int rr = 0; rr < NR; rr++) {
            int k = ranks[rr] - below[rr];
            unsigned cum = 0; int b = 0;
            for (; b < 2048; b++) { unsigned c = hist[rr][b]; if ((int)(cum + c) > k) break; cum += c; }
            pref[rr] |= (unsigned)b << 10;
            below[rr] += (int)cum;
        }
    }
    __syncthreads();

    // ---- pass 3: bits [9:0] ----
    for (int rr = 0; rr < NR; rr++)
        for (int i = tid; i < 1024; i += NBLK) hist[rr][i] = 0;
    __syncthreads();
    for (int i = tid; i < n; i += NBLK) {
        float f = data[i];
        if (TRUNC) f = truncf(f * 256.0f) * (1.0f / 256.0f);
        unsigned u = f2u(f);
        #pragma unroll
        for (int rr = 0; rr < NR; rr++)
            if ((u >> 10) == (pref[rr] >> 10))
                atomicAdd(&hist[rr][u & 1023], 1u);
    }
    __syncthreads();
    if (tid == 0) {
        for (int rr = 0; rr < NR; rr++) {
            int k = ranks[rr] - below[rr];
            unsigned cum = 0; int b = 0;
            for (; b < 1024; b++) { unsigned c = hist[rr][b]; if ((int)(cum + c) > k) break; cum += c; }
            vsel[rr] = pref[rr] | (unsigned)b;
            clt[rr]  = below[rr] + (int)cum;
            ceq[rr]  = (int)hist[rr][b];
            nmin[rr] = 0xFFFFFFFFu;
        }
    }
    __syncthreads();

    // ---- optional pass 4: min element strictly greater than selected value ----
    bool anynext = false;
    if (need_next)
        for (int rr = 0; rr < NR; rr++)
            if (ranks[rr] + 1 >= clt[rr] + ceq[rr]) anynext = true;
    if (anynext) {
        unsigned lmin[NR];
        #pragma unroll
        for (int rr = 0; rr < NR; rr++) lmin[rr] = 0xFFFFFFFFu;
        for (int i = tid; i < n; i += NBLK) {
            float f = data[i];
            if (TRUNC) f = truncf(f * 256.0f) * (1.0f / 256.0f);
            unsigned u = f2u(f);
            #pragma unroll
            for (int rr = 0; rr < NR; rr++)
                if (u > vsel[rr] && u < lmin[rr]) lmin[rr] = u;
        }
        #pragma unroll
        for (int rr = 0; rr < NR; rr++) atomicMin(&nmin[rr], lmin[rr]);
        __syncthreads();
    }

    #pragma unroll
    for (int rr = 0; rr < NR; rr++) {
        v_out[rr] = u2f(vsel[rr]);
        if (v1_out)
            v1_out[rr] = (ranks[rr] + 1 < clt[rr] + ceq[rr]) ? v_out[rr] : u2f(nmin[rr]);
    }
}

// ---------------------------------------------------------------------------
// kernels
// ---------------------------------------------------------------------------
__global__ void k1_kernel(const float* __restrict__ kern) {
    int i = threadIdx.x;
    if (i < FW) {
        float s = 0.0f;
        for (int j = 0; j < FW; j++) s += kern[i * FW + j];
        g_k1[i] = s;
    }
}

__global__ __launch_bounds__(NBLK)
void median_kernel(const float* __restrict__ x) {
    int ch = blockIdx.x;
    int ranks[1] = { (HW - 1) / 2 };
    float v[1];
    radix_select<1, false>(x + (size_t)ch * HW, HW, ranks, v, nullptr, false);
    if (threadIdx.x == 0) g_med[ch] = v[0] + 0.2f;
}

__global__ __launch_bounds__(1024)
void conv_kernel(const float* __restrict__ x, const float* __restrict__ mask) {
    __shared__ float s_in[SH][SH];        // 54x54 xp tile (with halo)
    __shared__ float s_tmp[SH][TILE + 1]; // horizontal-conv result, padded
    __shared__ float s_k[FW];

    const int tx = threadIdx.x, ty = threadIdx.y;
    const int tid = ty * 32 + tx;
    const int ch = blockIdx.z;
    const int nb = ch / 3;
    const int bx = blockIdx.x * TILE, by = blockIdx.y * TILE;

    if (tid < FW) s_k[tid] = g_k1[tid];

    const float* xc = x + (size_t)ch * HW;
    const float* mc = mask + (size_t)nb * HW;
    const float med = g_med[ch];

    for (int i = tid; i < SH * SH; i += 1024) {
        int r = i / SH, c = i % SH;
        int gy = min(max(by - PAD + r, 0), 511);
        int gx = min(max(bx - PAD + c, 0), 511);
        float xv = xc[gy * W + gx];
        float mv = mc[gy * W + gx];
        s_in[r][c] = mv * xv + (1.0f - mv) * med;
    }
    __syncthreads();

    // horizontal pass
    for (int r = ty; r < SH; r += 32) {
        float acc = 0.0f;
        #pragma unroll
        for (int j = 0; j < FW; j++) acc += s_in[r][tx + j] * s_k[j];
        s_tmp[r][tx] = acc;
    }
    __syncthreads();

    // vertical pass + res
    float acc = 0.0f;
    #pragma unroll
    for (int i = 0; i < FW; i++) acc += s_tmp[ty + i][tx] * s_k[i];
    float xp = s_in[ty + PAD][tx + PAD];
    g_res[(size_t)ch * HW + (by + ty) * W + (bx + tx)] = 4.0f * (xp - acc);
}

__global__ __launch_bounds__(NBLK)
void pct_kernel() {
    int ch = blockIdx.x;
    double p0 = (double)(HW - 1) * 0.03;
    double p1 = (double)(HW - 1) * 0.97;
    int ranks[2] = { (int)p0, (int)p1 };
    float fr[2] = { (float)(p0 - (double)ranks[0]), (float)(p1 - (double)ranks[1]) };
    float v[2], v1[2];
    radix_select<2, true>(g_res + (size_t)ch * HW, HW, ranks, v, v1, true);
    if (threadIdx.x == 0) {
        g_lo[ch] = v[0] + fr[0] * (v1[0] - v[0]);
        g_hi[ch] = v[1] + fr[1] * (v1[1] - v[1]);
    }
}

__global__ void final_kernel(const float* __restrict__ mask, float* __restrict__ out) {
    int ch = blockIdx.y;
    int nb = ch / 3;
    int i = blockIdx.x * blockDim.x + threadIdx.x;
    float lo = g_lo[ch], hi = g_hi[ch];
    float r = g_res[(size_t)ch * HW + i];
    out[(size_t)ch * HW + i] = (r - lo) / (hi - lo) * mask[(size_t)nb * HW + i];
}

// ---------------------------------------------------------------------------
extern "C" void kernel_launch(void* const* d_in, const int* in_sizes, int n_in,
                              void* d_out, int out_size) {
    const float* x    = (const float*)d_in[0];
    const float* mask = (const float*)d_in[1];
    const float* kern = (const float*)d_in[2];
    float* out = (float*)d_out;

    k1_kernel<<<1, 32>>>(kern);
    median_kernel<<<NCH, NBLK>>>(x);
    conv_kernel<<<dim3(W / TILE, W / TILE, NCH), dim3(32, 32)>>>(x, mask);
    pct_kernel<<<NCH, NBLK>>>();
    final_kernel<<<dim3(HW / 256, NCH), 256>>>(mask, out);
}

// round 2
// speedup vs baseline: 1.7152x; 1.7152x over previous
#include <cuda_runtime.h>

#define HW   (512*512)
#define W    512
#define NCH  48            // 16 batches * 3 channels
#define FW   23
#define PAD  11
#define TILE 32
#define SH   (TILE + 2*PAD)   // 54

#define MB   8192          // median histogram bins over [-8, 8)
#define PB   16384         // pct histogram bins: i=(int)(res*256), res in (-32,32)
#define CAP  16384         // median candidate capacity per channel
#define SEG  4             // data-pass blocks per channel

// scratch (no cudaMalloc allowed)
__device__ float    g_res[(size_t)NCH * HW];
__device__ unsigned g_mhist[NCH * MB];
__device__ unsigned g_phist[NCH * PB];
__device__ float    g_cand[NCH * CAP];
__device__ int      g_ccount[NCH];
__device__ int      g_selbin[NCH];
__device__ int      g_selrank[NCH];
__device__ float    g_med[NCH];
__device__ float    g_lo[NCH];
__device__ float    g_hi[NCH];
__device__ float    g_k1[FW];

// ---------------------------------------------------------------------------
__global__ void zero_kernel() {
    int i = blockIdx.x * blockDim.x + threadIdx.x;
    if (i < NCH * MB) g_mhist[i] = 0;
    if (i < NCH * PB) g_phist[i] = 0;
    if (i < NCH)      g_ccount[i] = 0;
}

__global__ void k1_kernel(const float* __restrict__ kern) {
    int i = threadIdx.x;
    if (i < FW) {
        float s = 0.0f;
        for (int j = 0; j < FW; j++) s += kern[i * FW + j];
        g_k1[i] = s;
    }
}

// ---------------------------------------------------------------------------
// median: value-binned histogram over [-8, 8), bin width 1/512
// ---------------------------------------------------------------------------
__device__ __forceinline__ int med_bin(float v) {
    int b = (int)floorf(fmaf(v, 512.0f, 4096.0f));
    return b < 0 ? 0 : (b > MB - 1 ? MB - 1 : b);
}

__global__ __launch_bounds__(1024)
void med_hist(const float* __restrict__ x) {
    __shared__ unsigned sh[MB];                       // 32 KB
    const int ch = blockIdx.x / SEG, seg = blockIdx.x % SEG;
    const int tid = threadIdx.x;
    for (int i = tid; i < MB; i += 1024) sh[i] = 0;
    __syncthreads();
    const float4* p = (const float4*)(x + (size_t)ch * HW) + (size_t)seg * (HW / 4 / SEG);
    for (int i = tid; i < HW / 4 / SEG; i += 1024) {
        float4 v = p[i];
        atomicAdd(&sh[med_bin(v.x)], 1u);
        atomicAdd(&sh[med_bin(v.y)], 1u);
        atomicAdd(&sh[med_bin(v.z)], 1u);
        atomicAdd(&sh[med_bin(v.w)], 1u);
    }
    __syncthreads();
    unsigned* gh = g_mhist + ch * MB;
    for (int i = tid; i < MB; i += 1024) {
        unsigned c = sh[i];
        if (c) atomicAdd(&gh[i], c);
    }
}

__global__ __launch_bounds__(1024)
void med_scan() {
    __shared__ unsigned ssum[1024];
    __shared__ unsigned spref[1025];
    const int ch = blockIdx.x, tid = threadIdx.x;
    const unsigned* h = g_mhist + ch * MB;
    unsigned s = 0;
    #pragma unroll
    for (int j = 0; j < MB / 1024; j++) s += h[tid * (MB / 1024) + j];
    ssum[tid] = s;
    __syncthreads();
    if (tid == 0) {
        unsigned c = 0;
        for (int i = 0; i < 1024; i++) { spref[i] = c; c += ssum[i]; }
        spref[1024] = c;
    }
    __syncthreads();
    const unsigned k = (HW - 1) / 2;
    if (spref[tid] <= k && k < spref[tid + 1]) {
        unsigned cum = spref[tid];
        for (int j = 0; j < MB / 1024; j++) {
            int b = tid * (MB / 1024) + j;
            unsigned c = h[b];
            if (cum + c > k) { g_selbin[ch] = b; g_selrank[ch] = (int)(k - cum); break; }
            cum += c;
        }
    }
}

__global__ __launch_bounds__(1024)
void med_collect(const float* __restrict__ x) {
    const int ch = blockIdx.x / SEG, seg = blockIdx.x % SEG;
    const int tid = threadIdx.x;
    const int sb = g_selbin[ch];
    const float4* p = (const float4*)(x + (size_t)ch * HW) + (size_t)seg * (HW / 4 / SEG);
    for (int i = tid; i < HW / 4 / SEG; i += 1024) {
        float4 v = p[i];
        float vv[4] = { v.x, v.y, v.z, v.w };
        #pragma unroll
        for (int j = 0; j < 4; j++) {
            if (med_bin(vv[j]) == sb) {
                int pp = atomicAdd(&g_ccount[ch], 1);
                if (pp < CAP) g_cand[ch * CAP + pp] = vv[j];
            }
        }
    }
}

__global__ __launch_bounds__(1024)
void med_select() {
    const int ch = blockIdx.x, tid = threadIdx.x;
    int n = g_ccount[ch];
    if (n > CAP) n = CAP;
    const int k = g_selrank[ch];
    const float* c = g_cand + ch * CAP;
    for (int i = tid; i < n; i += 1024) {
        float vi = c[i];
        int r = 0;
        for (int j = 0; j < n; j++) {
            float vj = c[j];
            r += (vj < vi) || (vj == vi && j < i);
        }
        if (r == k) g_med[ch] = vi + 0.2f;
    }
}

// ---------------------------------------------------------------------------
// separable conv (mask-mix fused into tile load)
// ---------------------------------------------------------------------------
__global__ __launch_bounds__(1024)
void conv_kernel(const float* __restrict__ x, const float* __restrict__ mask) {
    __shared__ float s_in[SH][SH];
    __shared__ float s_tmp[SH][TILE + 1];
    __shared__ float s_k[FW];

    const int tx = threadIdx.x, ty = threadIdx.y;
    const int tid = ty * 32 + tx;
    const int ch = blockIdx.z;
    const int nb = ch / 3;
    const int bx = blockIdx.x * TILE, by = blockIdx.y * TILE;

    if (tid < FW) s_k[tid] = g_k1[tid];

    const float* xc = x + (size_t)ch * HW;
    const float* mc = mask + (size_t)nb * HW;
    const float med = g_med[ch];

    for (int i = tid; i < SH * SH; i += 1024) {
        int r = i / SH, c = i % SH;
        int gy = min(max(by - PAD + r, 0), 511);
        int gx = min(max(bx - PAD + c, 0), 511);
        float xv = xc[gy * W + gx];
        float mv = mc[gy * W + gx];
        s_in[r][c] = mv * xv + (1.0f - mv) * med;
    }
    __syncthreads();

    for (int r = ty; r < SH; r += 32) {
        float acc = 0.0f;
        #pragma unroll
        for (int j = 0; j < FW; j++) acc += s_in[r][tx + j] * s_k[j];
        s_tmp[r][tx] = acc;
    }
    __syncthreads();

    float acc = 0.0f;
    #pragma unroll
    for (int i = 0; i < FW; i++) acc += s_tmp[ty + i][tx] * s_k[i];
    float xp = s_in[ty + PAD][tx + PAD];
    g_res[(size_t)ch * HW + (by + ty) * W + (bx + tx)] = 4.0f * (xp - acc);
}

// ---------------------------------------------------------------------------
// percentile: exact via integer-quantized histogram (temp = i/256)
// ---------------------------------------------------------------------------
__global__ __launch_bounds__(1024)
void pct_hist() {
    extern __shared__ unsigned sh[];                  // PB * 4 = 64 KB dynamic
    const int ch = blockIdx.x / SEG, seg = blockIdx.x % SEG;
    const int tid = threadIdx.x;
    for (int i = tid; i < PB; i += 1024) sh[i] = 0;
    __syncthreads();
    const float4* p = (const float4*)(g_res + (size_t)ch * HW) + (size_t)seg * (HW / 4 / SEG);
    for (int i = tid; i < HW / 4 / SEG; i += 1024) {
        float4 v = p[i];
        int b0 = (int)(v.x * 256.0f) + PB / 2; b0 = b0 < 0 ? 0 : (b0 > PB - 1 ? PB - 1 : b0);
        int b1 = (int)(v.y * 256.0f) + PB / 2; b1 = b1 < 0 ? 0 : (b1 > PB - 1 ? PB - 1 : b1);
        int b2 = (int)(v.z * 256.0f) + PB / 2; b2 = b2 < 0 ? 0 : (b2 > PB - 1 ? PB - 1 : b2);
        int b3 = (int)(v.w * 256.0f) + PB / 2; b3 = b3 < 0 ? 0 : (b3 > PB - 1 ? PB - 1 : b3);
        atomicAdd(&sh[b0], 1u);
        atomicAdd(&sh[b1], 1u);
        atomicAdd(&sh[b2], 1u);
        atomicAdd(&sh[b3], 1u);
    }
    __syncthreads();
    unsigned* gh = g_phist + ch * PB;
    for (int i = tid; i < PB; i += 1024) {
        unsigned c = sh[i];
        if (c) atomicAdd(&gh[i], c);
    }
}

__global__ __launch_bounds__(1024)
void pct_scan() {
    __shared__ unsigned ssum[1024];
    __shared__ unsigned spref[1025];
    const int ch = blockIdx.x, tid = threadIdx.x;
    const unsigned* h = g_phist + ch * PB;
    unsigned s = 0;
    #pragma unroll
    for (int j = 0; j < PB / 1024; j++) s += h[tid * (PB / 1024) + j];
    ssum[tid] = s;
    __syncthreads();
    if (tid == 0) {
        unsigned c = 0;
        for (int i = 0; i < 1024; i++) { spref[i] = c; c += ssum[i]; }
        spref[1024] = c;
    }
    __syncthreads();

    const double n1 = (double)(HW - 1);
    for (int rsel = 0; rsel < 2; rsel++) {
        double pos = n1 * (rsel ? 0.97 : 0.03);
        unsigned k = (unsigned)pos;
        float fr = (float)(pos - (double)k);
        if (spref[tid] <= k && k < spref[tid + 1]) {
            unsigned cum = spref[tid];
            for (int j = 0; j < PB / 1024; j++) {
                int b = tid * (PB / 1024) + j;
                unsigned c = h[b];
                if (cum + c > k) {
                    float v = (float)(b - PB / 2) * (1.0f / 256.0f);
                    float v1 = v;
                    if (k + 1 >= cum + c) {               // next value in a later bin
                        int b2 = b + 1;
                        while (b2 < PB && h[b2] == 0) b2++;
                        if (b2 < PB) v1 = (float)(b2 - PB / 2) * (1.0f / 256.0f);
                    }
                    float out = v + fr * (v1 - v);
                    if (rsel) g_hi[ch] = out; else g_lo[ch] = out;
                    break;
                }
                cum += c;
            }
        }
    }
}

// ---------------------------------------------------------------------------
__global__ void final_kernel(const float* __restrict__ mask, float* __restrict__ out) {
    const int ch = blockIdx.y;
    const int nb = ch / 3;
    const int i = blockIdx.x * blockDim.x + threadIdx.x;   // float4 index
    const float lo = g_lo[ch], hi = g_hi[ch];
    const float inv = 1.0f / (hi - lo);
    float4 r = ((const float4*)(g_res + (size_t)ch * HW))[i];
    float4 m = ((const float4*)(mask + (size_t)nb * HW))[i];
    float4 o;
    o.x = (r.x - lo) * inv * m.x;
    o.y = (r.y - lo) * inv * m.y;
    o.z = (r.z - lo) * inv * m.z;
    o.w = (r.w - lo) * inv * m.w;
    ((float4*)out)[(size_t)ch * (HW / 4) + i] = o;
}

// ---------------------------------------------------------------------------
extern "C" void kernel_launch(void* const* d_in, const int* in_sizes, int n_in,
                              void* d_out, int out_size) {
    const float* x    = (const float*)d_in[0];
    const float* mask = (const float*)d_in[1];
    const float* kern = (const float*)d_in[2];
    float* out = (float*)d_out;

    cudaFuncSetAttribute(pct_hist, cudaFuncAttributeMaxDynamicSharedMemorySize, PB * 4);

    zero_kernel<<<(NCH * PB + 1023) / 1024, 1024>>>();
    k1_kernel<<<1, 32>>>(kern);
    med_hist<<<NCH * SEG, 1024>>>(x);
    med_scan<<<NCH, 1024>>>();
    med_collect<<<NCH * SEG, 1024>>>(x);
    med_select<<<NCH, 1024>>>();
    conv_kernel<<<dim3(W / TILE, W / TILE, NCH), dim3(32, 32), 0>>>(x, mask);
    pct_hist<<<NCH * SEG, 1024, PB * 4>>>();
    pct_scan<<<NCH, 1024>>>();
    final_kernel<<<dim3(HW / 4 / 256, NCH), 256>>>(mask, out);
}

// round 3
// speedup vs baseline: 2.5561x; 1.4903x over previous
#include <cuda_runtime.h>

#define HW   (512*512)
#define W    512
#define NCH  48            // 16 batches * 3 channels
#define FW   23
#define PAD  11

#define MB   8192          // median histogram bins over [-8, 8)
#define PB   16384         // pct histogram bins: i=(int)(res*256), res in (-32,32)
#define CAP  16384         // median candidate capacity per channel
#define SEG  8             // data-pass blocks per channel

// conv tiling
#define CTX  64
#define CTY  64
#define CSH  (CTX + 2*PAD)   // 86
#define CTHREADS 512

// scratch (no cudaMalloc allowed)
__device__ float    g_res[(size_t)NCH * HW];
__device__ unsigned g_mhist[NCH * MB];
__device__ unsigned g_phist[NCH * PB];
__device__ float    g_cand[NCH * CAP];
__device__ int      g_ccount[NCH];
__device__ int      g_selbin[NCH];
__device__ int      g_selrank[NCH];
__device__ float    g_med[NCH];
__device__ float    g_lo[NCH];
__device__ float    g_hi[NCH];
__device__ float    g_k1[FW];

// ---------------------------------------------------------------------------
__global__ void zero_kernel() {
    int i = blockIdx.x * blockDim.x + threadIdx.x;
    if (i < NCH * MB) g_mhist[i] = 0;
    if (i < NCH * PB) g_phist[i] = 0;
    if (i < NCH)      g_ccount[i] = 0;
}

__global__ void k1_kernel(const float* __restrict__ kern) {
    int i = threadIdx.x;
    if (i < FW) {
        float s = 0.0f;
        for (int j = 0; j < FW; j++) s += kern[i * FW + j];
        g_k1[i] = s;
    }
}

// ---------------------------------------------------------------------------
// block-wide exclusive scan over 1024 threads (shuffle-based)
// ---------------------------------------------------------------------------
__device__ __forceinline__ unsigned block_excl_scan_1024(unsigned val) {
    __shared__ unsigned warpsum[32];
    const unsigned lane = threadIdx.x & 31, wid = threadIdx.x >> 5;
    unsigned s = val;
    #pragma unroll
    for (int o = 1; o < 32; o <<= 1) {
        unsigned t = __shfl_up_sync(0xFFFFFFFFu, s, o);
        if (lane >= o) s += t;
    }
    if (lane == 31) warpsum[wid] = s;
    __syncthreads();
    if (wid == 0) {
        unsigned w = warpsum[lane];
        #pragma unroll
        for (int o = 1; o < 32; o <<= 1) {
            unsigned t = __shfl_up_sync(0xFFFFFFFFu, w, o);
            if (lane >= o) w += t;
        }
        warpsum[lane] = w;
    }
    __syncthreads();
    unsigned wexcl = wid ? warpsum[wid - 1] : 0u;
    return wexcl + s - val;
}

// ---------------------------------------------------------------------------
// median: value-binned histogram over [-8, 8), bin width 1/512
// ---------------------------------------------------------------------------
__device__ __forceinline__ int med_bin(float v) {
    int b = (int)floorf(fmaf(v, 512.0f, 4096.0f));
    return b < 0 ? 0 : (b > MB - 1 ? MB - 1 : b);
}

__global__ __launch_bounds__(512)
void med_hist(const float* __restrict__ x) {
    __shared__ unsigned sh[MB];                       // 32 KB
    const int ch = blockIdx.x / SEG, seg = blockIdx.x % SEG;
    const int tid = threadIdx.x;
    for (int i = tid; i < MB; i += 512) sh[i] = 0;
    __syncthreads();
    const float4* p = (const float4*)(x + (size_t)ch * HW) + (size_t)seg * (HW / 4 / SEG);
    for (int i = tid; i < HW / 4 / SEG; i += 512) {
        float4 v = p[i];
        atomicAdd(&sh[med_bin(v.x)], 1u);
        atomicAdd(&sh[med_bin(v.y)], 1u);
        atomicAdd(&sh[med_bin(v.z)], 1u);
        atomicAdd(&sh[med_bin(v.w)], 1u);
    }
    __syncthreads();
    unsigned* gh = g_mhist + ch * MB;
    for (int i = tid; i < MB; i += 512) {
        unsigned c = sh[i];
        if (c) atomicAdd(&gh[i], c);
    }
}

__global__ __launch_bounds__(1024)
void med_scan() {
    const int ch = blockIdx.x, tid = threadIdx.x;
    const unsigned* h = g_mhist + ch * MB;
    unsigned loc[MB / 1024];
    unsigned s = 0;
    #pragma unroll
    for (int j = 0; j < MB / 1024; j++) { loc[j] = h[tid * (MB / 1024) + j]; s += loc[j]; }
    unsigned pref = block_excl_scan_1024(s);
    const unsigned k = (HW - 1) / 2;
    if (pref <= k && k < pref + s) {
        unsigned cum = pref;
        #pragma unroll
        for (int j = 0; j < MB / 1024; j++) {
            unsigned c = loc[j];
            if (cum + c > k) { g_selbin[ch] = tid * (MB / 1024) + j; g_selrank[ch] = (int)(k - cum); break; }
            cum += c;
        }
    }
}

__global__ __launch_bounds__(512)
void med_collect(const float* __restrict__ x) {
    const int ch = blockIdx.x / SEG, seg = blockIdx.x % SEG;
    const int tid = threadIdx.x;
    const int sb = g_selbin[ch];
    const float4* p = (const float4*)(x + (size_t)ch * HW) + (size_t)seg * (HW / 4 / SEG);
    for (int i = tid; i < HW / 4 / SEG; i += 512) {
        float4 v = p[i];
        float vv[4] = { v.x, v.y, v.z, v.w };
        #pragma unroll
        for (int j = 0; j < 4; j++) {
            if (med_bin(vv[j]) == sb) {
                int pp = atomicAdd(&g_ccount[ch], 1);
                if (pp < CAP) g_cand[ch * CAP + pp] = vv[j];
            }
        }
    }
}

__global__ __launch_bounds__(1024)
void med_select() {
    const int ch = blockIdx.x, tid = threadIdx.x;
    int n = g_ccount[ch];
    if (n > CAP) n = CAP;
    const int k = g_selrank[ch];
    const float* c = g_cand + ch * CAP;
    for (int i = tid; i < n; i += 1024) {
        float vi = c[i];
        int r = 0;
        for (int j = 0; j < n; j++) {
            float vj = c[j];
            r += (vj < vi) || (vj == vi && j < i);
        }
        if (r == k) g_med[ch] = vi + 0.2f;
    }
}

// ---------------------------------------------------------------------------
// separable conv, 64x64 tile (mask-mix fused into tile load)
// ---------------------------------------------------------------------------
__global__ __launch_bounds__(CTHREADS)
void conv_kernel(const float* __restrict__ x, const float* __restrict__ mask) {
    extern __shared__ float dsm[];
    float* s_in  = dsm;                    // CSH * CSH
    float* s_tmp = dsm + CSH * CSH;        // CSH * CTX
    __shared__ float s_k[FW];

    const int tid = threadIdx.x;
    const int ch = blockIdx.z;
    const int nb = ch / 3;
    const int bx = blockIdx.x * CTX, by = blockIdx.y * CTY;

    if (tid < FW) s_k[tid] = g_k1[tid];

    const float* xc = x + (size_t)ch * HW;
    const float* mc = mask + (size_t)nb * HW;
    const float med = g_med[ch];

    for (int i = tid; i < CSH * CSH; i += CTHREADS) {
        int r = i / CSH, c = i % CSH;
        int gy = min(max(by - PAD + r, 0), 511);
        int gx = min(max(bx - PAD + c, 0), 511);
        float xv = xc[gy * W + gx];
        float mv = mc[gy * W + gx];
        s_in[r * CSH + c] = mv * xv + (1.0f - mv) * med;
    }
    __syncthreads();

    // horizontal pass: s_tmp[r][c] for r in [0,CSH), c in [0,CTX)
    for (int idx = tid; idx < CSH * CTX; idx += CTHREADS) {
        int r = idx / CTX, c = idx % CTX;
        const float* row = s_in + r * CSH + c;
        float acc = 0.0f;
        #pragma unroll
        for (int j = 0; j < FW; j++) acc += row[j] * s_k[j];
        s_tmp[r * CTX + c] = acc;
    }
    __syncthreads();

    // vertical pass + res
    for (int idx = tid; idx < CTX * CTY; idx += CTHREADS) {
        int y = idx / CTX, xx = idx % CTX;
        float acc = 0.0f;
        #pragma unroll
        for (int i = 0; i < FW; i++) acc += s_tmp[(y + i) * CTX + xx] * s_k[i];
        float xp = s_in[(y + PAD) * CSH + (xx + PAD)];
        g_res[(size_t)ch * HW + (by + y) * W + (bx + xx)] = 4.0f * (xp - acc);
    }
}

// ---------------------------------------------------------------------------
// percentile: exact via integer-quantized histogram (temp = i/256)
// ---------------------------------------------------------------------------
__global__ __launch_bounds__(512)
void pct_hist() {
    extern __shared__ unsigned shp[];                 // PB * 4 = 64 KB dynamic
    const int ch = blockIdx.x / SEG, seg = blockIdx.x % SEG;
    const int tid = threadIdx.x;
    for (int i = tid; i < PB; i += 512) shp[i] = 0;
    __syncthreads();
    const float4* p = (const float4*)(g_res + (size_t)ch * HW) + (size_t)seg * (HW / 4 / SEG);
    for (int i = tid; i < HW / 4 / SEG; i += 512) {
        float4 v = p[i];
        int b0 = (int)(v.x * 256.0f) + PB / 2; b0 = b0 < 0 ? 0 : (b0 > PB - 1 ? PB - 1 : b0);
        int b1 = (int)(v.y * 256.0f) + PB / 2; b1 = b1 < 0 ? 0 : (b1 > PB - 1 ? PB - 1 : b1);
        int b2 = (int)(v.z * 256.0f) + PB / 2; b2 = b2 < 0 ? 0 : (b2 > PB - 1 ? PB - 1 : b2);
        int b3 = (int)(v.w * 256.0f) + PB / 2; b3 = b3 < 0 ? 0 : (b3 > PB - 1 ? PB - 1 : b3);
        atomicAdd(&shp[b0], 1u);
        atomicAdd(&shp[b1], 1u);
        atomicAdd(&shp[b2], 1u);
        atomicAdd(&shp[b3], 1u);
    }
    __syncthreads();
    unsigned* gh = g_phist + ch * PB;
    for (int i = tid; i < PB; i += 512) {
        unsigned c = shp[i];
        if (c) atomicAdd(&gh[i], c);
    }
}

__global__ __launch_bounds__(1024)
void pct_scan() {
    const int ch = blockIdx.x, tid = threadIdx.x;
    const unsigned* h = g_phist + ch * PB;
    unsigned loc[PB / 1024];
    unsigned s = 0;
    #pragma unroll
    for (int j = 0; j < PB / 1024; j++) { loc[j] = h[tid * (PB / 1024) + j]; s += loc[j]; }
    unsigned pref = block_excl_scan_1024(s);

    const double n1 = (double)(HW - 1);
    #pragma unroll
    for (int rsel = 0; rsel < 2; rsel++) {
        double pos = n1 * (rsel ? 0.97 : 0.03);
        unsigned k = (unsigned)pos;
        float fr = (float)(pos - (double)k);
        if (pref <= k && k < pref + s) {
            unsigned cum = pref;
            #pragma unroll
            for (int j = 0; j < PB / 1024; j++) {
                unsigned c = loc[j];
                int b = tid * (PB / 1024) + j;
                if (cum + c > k) {
                    float v = (float)(b - PB / 2) * (1.0f / 256.0f);
                    float v1 = v;
                    if (k + 1 >= cum + c) {               // next value in a later bin
                        int b2 = b + 1;
                        while (b2 < PB && h[b2] == 0) b2++;
                        if (b2 < PB) v1 = (float)(b2 - PB / 2) * (1.0f / 256.0f);
                    }
                    float out = v + fr * (v1 - v);
                    if (rsel) g_hi[ch] = out; else g_lo[ch] = out;
                    break;
                }
                cum += c;
            }
        }
    }
}

// ---------------------------------------------------------------------------
__global__ void final_kernel(const float* __restrict__ mask, float* __restrict__ out) {
    const int ch = blockIdx.y;
    const int nb = ch / 3;
    const int i = blockIdx.x * blockDim.x + threadIdx.x;   // float4 index
    const float lo = g_lo[ch], hi = g_hi[ch];
    const float inv = 1.0f / (hi - lo);
    float4 r = ((const float4*)(g_res + (size_t)ch * HW))[i];
    float4 m = ((const float4*)(mask + (size_t)nb * HW))[i];
    float4 o;
    o.x = (r.x - lo) * inv * m.x;
    o.y = (r.y - lo) * inv * m.y;
    o.z = (r.z - lo) * inv * m.z;
    o.w = (r.w - lo) * inv * m.w;
    ((float4*)out)[(size_t)ch * (HW / 4) + i] = o;
}

// ---------------------------------------------------------------------------
extern "C" void kernel_launch(void* const* d_in, const int* in_sizes, int n_in,
                              void* d_out, int out_size) {
    const float* x    = (const float*)d_in[0];
    const float* mask = (const float*)d_in[1];
    const float* kern = (const float*)d_in[2];
    float* out = (float*)d_out;

    static int init = 0;
    if (!init) {
        cudaFuncSetAttribute(pct_hist, cudaFuncAttributeMaxDynamicSharedMemorySize, PB * 4);
        cudaFuncSetAttribute(conv_kernel, cudaFuncAttributeMaxDynamicSharedMemorySize,
                             (CSH * CSH + CSH * CTX) * 4);
        init = 1;
    }

    zero_kernel<<<(NCH * PB + 1023) / 1024, 1024>>>();
    k1_kernel<<<1, 32>>>(kern);
    med_hist<<<NCH * SEG, 512>>>(x);
    med_scan<<<NCH, 1024>>>();
    med_collect<<<NCH * SEG, 512>>>(x);
    med_select<<<NCH, 1024>>>();
    conv_kernel<<<dim3(W / CTX, W / CTY, NCH), CTHREADS, (CSH * CSH + CSH * CTX) * 4>>>(x, mask);
    pct_hist<<<NCH * SEG, 512, PB * 4>>>();
    pct_scan<<<NCH, 1024>>>();
    final_kernel<<<dim3(HW / 4 / 256, NCH), 256>>>(mask, out);
}